// round 14
// baseline (speedup 1.0000x reference)
#include <cuda_runtime.h>

// ---------------------------------------------------------------------------
// RModel_29257317221019: fused cos-MLP deform (3->32->32->32->3) + trilinear
// sample from 256^3 volume.
// EXACTLY the R9 winner (2 pts/thread, f32x2 over output pairs, weights in
// __constant__ with plain element indexing -> immediate-offset LDC), with ONE
// change: layer-3 weights live in __shared__ and are read with inline-asm
// ld.shared.v2.b64 (register base + immediate offset -> no IMAD), halving
// constant-port demand.
// ---------------------------------------------------------------------------

typedef unsigned long long u64;

__device__ __forceinline__ void upk2(u64 v, float& lo, float& hi) {
    asm("mov.b64 {%0, %1}, %2;" : "=f"(lo), "=f"(hi) : "l"(v));
}
__device__ __forceinline__ u64 pk2(float lo, float hi) {
    u64 r; asm("mov.b64 %0, {%1, %2};" : "=l"(r) : "f"(lo), "f"(hi)); return r;
}
__device__ __forceinline__ u64 dup2(float v) {
    u64 r; asm("mov.b64 %0, {%1, %1};" : "=l"(r) : "f"(v)); return r;
}
__device__ __forceinline__ u64 ffma2(u64 a, u64 b, u64 c) {
    u64 r; asm("fma.rn.f32x2 %0, %1, %2, %3;" : "=l"(r) : "l"(a), "l"(b), "l"(c)); return r;
}
__device__ __forceinline__ void lds_v2b64(unsigned addr, u64& a, u64& b) {
    asm("ld.shared.v2.b64 {%0, %1}, [%2];" : "=l"(a), "=l"(b) : "r"(addr));
}

// Weights in constant memory (u64 = f32x2 operand pairs, raw layouts):
__constant__ u64 cW1[3][16];
__constant__ u64 cB1[16];
__constant__ u64 cW2[32][16];
__constant__ u64 cB2[16];
__constant__ u64 cB3[16];
// Final layer, prepacked by prep_kernel:
//   cWfP[2k] = (Wf[k][0], Wf[k][1]), cWfP[2k+1] = (Wf[k][2], 0)
//   cWfP[64] = (bf0, bf1),           cWfP[65]   = (bf2, 0)
__constant__ u64 cWfP[66];

__device__ u64 g_wf_scratch[66];

__global__ void prep_kernel(const float* __restrict__ Wf,
                            const float* __restrict__ bf) {
    int k = threadIdx.x;
    if (k < 32) {
        g_wf_scratch[2 * k]     = pk2(Wf[3 * k + 0], Wf[3 * k + 1]);
        g_wf_scratch[2 * k + 1] = pk2(Wf[3 * k + 2], 0.0f);
    }
    if (k == 0) {
        g_wf_scratch[64] = pk2(bf[0], bf[1]);
        g_wf_scratch[65] = pk2(bf[2], 0.0f);
    }
}

#define BLK 128

__global__ __launch_bounds__(BLK, 4)
void deform_sample_kernel(
    const float* __restrict__ x,
    const float* __restrict__ W3,
    const float* __restrict__ vol,
    float* __restrict__ out,
    int npairs)
{
    // Layer-3 weights in shared memory: raw row-major floats as 512 u64
    __shared__ __align__(16) u64 sW3[32 * 16];
    {
        const u64* w3u = reinterpret_cast<const u64*>(W3);
        for (int i = threadIdx.x; i < 512; i += BLK) sW3[i] = w3u[i];
    }
    __syncthreads();
    unsigned s3 = (unsigned)__cvta_generic_to_shared((void*)sW3);

    int t = blockIdx.x * blockDim.x + threadIdx.x;
    if (t >= npairs) return;

    // Two consecutive points (x layout: 4 floats/point, coords in [0:3])
    const float4* x4 = reinterpret_cast<const float4*>(x);
    float4 XA = x4[2 * t + 0];
    float4 XB = x4[2 * t + 1];

    float hA[32], hB[32];
    u64 aA[16], aB[16];

    // ---- Layer 1: h = cos(c @ W1 + b1) (constant, element indexing) ----
    {
        u64 cA0 = dup2(XA.x), cA1 = dup2(XA.y), cA2 = dup2(XA.z);
        u64 cB0 = dup2(XB.x), cB1v = dup2(XB.y), cB2v = dup2(XB.z);
#pragma unroll
        for (int q = 0; q < 8; q++) {           // d = 4q .. 4q+3  (j = 2q, 2q+1)
            u64 b0 = cB1[2 * q], b1p = cB1[2 * q + 1];
            u64 pA0 = b0, pA1 = b1p, pB0 = b0, pB1 = b1p;
#pragma unroll
            for (int c = 0; c < 3; c++) {
                u64 w0 = cW1[c][2 * q];
                u64 w1p = cW1[c][2 * q + 1];
                u64 ca = (c == 0) ? cA0 : (c == 1) ? cA1 : cA2;
                u64 cb = (c == 0) ? cB0 : (c == 1) ? cB1v : cB2v;
                pA0 = ffma2(ca, w0, pA0);
                pA1 = ffma2(ca, w1p, pA1);
                pB0 = ffma2(cb, w0, pB0);
                pB1 = ffma2(cb, w1p, pB1);
            }
            float lo, hi;
            upk2(pA0, lo, hi); hA[4*q]   = __cosf(lo); hA[4*q+1] = __cosf(hi);
            upk2(pA1, lo, hi); hA[4*q+2] = __cosf(lo); hA[4*q+3] = __cosf(hi);
            upk2(pB0, lo, hi); hB[4*q]   = __cosf(lo); hB[4*q+1] = __cosf(hi);
            upk2(pB1, lo, hi); hB[4*q+2] = __cosf(lo); hB[4*q+3] = __cosf(hi);
        }
    }

    // ---- Layer 2: h = cos(h @ W2 + b2) (constant, element indexing) ----
#pragma unroll
    for (int j = 0; j < 16; j++) { u64 b = cB2[j]; aA[j] = b; aB[j] = b; }
#pragma unroll
    for (int k = 0; k < 32; k++) {
        u64 dA = dup2(hA[k]);
        u64 dB = dup2(hB[k]);
#pragma unroll
        for (int j = 0; j < 16; j++) {
            u64 w = cW2[k][j];
            aA[j] = ffma2(dA, w, aA[j]);
            aB[j] = ffma2(dB, w, aB[j]);
        }
    }
#pragma unroll
    for (int p = 0; p < 16; p++) {
        float lo, hi;
        upk2(aA[p], lo, hi); hA[2*p] = __cosf(lo); hA[2*p+1] = __cosf(hi);
        upk2(aB[p], lo, hi); hB[2*p] = __cosf(lo); hB[2*p+1] = __cosf(hi);
    }

    // ---- Layer 3: h = cos(h @ W3 + b3) (shared, inline-asm LDS) ----
#pragma unroll
    for (int j = 0; j < 16; j++) { u64 b = cB3[j]; aA[j] = b; aB[j] = b; }
#pragma unroll
    for (int k = 0; k < 32; k++) {
        u64 dA = dup2(hA[k]);
        u64 dB = dup2(hB[k]);
#pragma unroll
        for (int m = 0; m < 4; m++) {
            u64 w0, w1, w2, w3v;
            lds_v2b64(s3 + k * 128 + m * 32,      w0, w1);  // j = 4m, 4m+1
            lds_v2b64(s3 + k * 128 + m * 32 + 16, w2, w3v); // j = 4m+2, 4m+3
            aA[4*m]   = ffma2(dA, w0, aA[4*m]);
            aA[4*m+1] = ffma2(dA, w1, aA[4*m+1]);
            aA[4*m+2] = ffma2(dA, w2, aA[4*m+2]);
            aA[4*m+3] = ffma2(dA, w3v, aA[4*m+3]);
            aB[4*m]   = ffma2(dB, w0, aB[4*m]);
            aB[4*m+1] = ffma2(dB, w1, aB[4*m+1]);
            aB[4*m+2] = ffma2(dB, w2, aB[4*m+2]);
            aB[4*m+3] = ffma2(dB, w3v, aB[4*m+3]);
        }
    }
#pragma unroll
    for (int p = 0; p < 16; p++) {
        float lo, hi;
        upk2(aA[p], lo, hi); hA[2*p] = __cosf(lo); hA[2*p+1] = __cosf(hi);
        upk2(aB[p], lo, hi); hB[2*p] = __cosf(lo); hB[2*p+1] = __cosf(hi);
    }

    // ---- Final: coord = c + 5 * (h @ Wf + bf) (constant, element idx) ----
    float pxy[2][3];
    {
        u64 eA01 = cWfP[64], eA2 = cWfP[65];
        u64 eB01 = eA01,     eB2 = eA2;
#pragma unroll
        for (int k = 0; k < 32; k++) {
            u64 w01 = cWfP[2 * k];
            u64 w2x = cWfP[2 * k + 1];
            u64 dA = dup2(hA[k]);
            u64 dB = dup2(hB[k]);
            eA01 = ffma2(dA, w01, eA01);
            eA2  = ffma2(dA, w2x, eA2);
            eB01 = ffma2(dB, w01, eB01);
            eB2  = ffma2(dB, w2x, eB2);
        }
        float f0, f1, f2, jk;
        upk2(eA01, f0, f1); upk2(eA2, f2, jk);
        pxy[0][0] = fmaf(5.0f, f0, XA.x);
        pxy[0][1] = fmaf(5.0f, f1, XA.y);
        pxy[0][2] = fmaf(5.0f, f2, XA.z);
        upk2(eB01, f0, f1); upk2(eB2, f2, jk);
        pxy[1][0] = fmaf(5.0f, f0, XB.x);
        pxy[1][1] = fmaf(5.0f, f1, XB.y);
        pxy[1][2] = fmaf(5.0f, f2, XB.z);
    }

    // ---- Trilinear sample (scalar per point) ----
    float res[2];
#pragma unroll
    for (int s = 0; s < 2; s++) {
        float cx = fminf(fmaxf(pxy[s][0], 0.0f), 255.0f);
        float cy = fminf(fmaxf(pxy[s][1], 0.0f), 255.0f);
        float cz = fminf(fmaxf(pxy[s][2], 0.0f), 255.0f);

        float fx0 = floorf(cx), fy0 = floorf(cy), fz0 = floorf(cz);
        int ix0 = (int)fx0, iy0 = (int)fy0, iz0 = (int)fz0;
        int ix1 = min(ix0 + 1, 255);
        int iy1 = min(iy0 + 1, 255);
        int iz1 = min(iz0 + 1, 255);

        float fx = cx - fx0, fy = cy - fy0, fz = cz - fz0;
        float gx = 1.0f - fx, gy = 1.0f - fy, gz = 1.0f - fz;

        int X0 = ix0 << 16, X1 = ix1 << 16;
        int Y0 = iy0 << 8,  Y1 = iy1 << 8;

        float v000 = __ldg(vol + (X0 + Y0 + iz0));
        float v100 = __ldg(vol + (X1 + Y0 + iz0));
        float v010 = __ldg(vol + (X0 + Y1 + iz0));
        float v001 = __ldg(vol + (X0 + Y0 + iz1));
        float v110 = __ldg(vol + (X1 + Y1 + iz0));
        float v101 = __ldg(vol + (X1 + Y0 + iz1));
        float v011 = __ldg(vol + (X0 + Y1 + iz1));
        float v111 = __ldg(vol + (X1 + Y1 + iz1));

        float r;
        r  = v000 * (gx * gy * gz);
        r += v100 * (fx * gy * gz);
        r += v010 * (gx * fy * gz);
        r += v001 * (gx * gy * fz);
        r += v110 * (fx * fy * gz);
        r += v101 * (fx * gy * fz);
        r += v011 * (gx * fy * fz);
        r += v111 * (fx * fy * fz);
        res[s] = r;
    }

    float2 o; o.x = res[0]; o.y = res[1];
    reinterpret_cast<float2*>(out)[t] = o;
}

extern "C" void kernel_launch(void* const* d_in, const int* in_sizes, int n_in,
                              void* d_out, int out_size) {
    const float* x   = (const float*)d_in[0];
    const float* W3g = (const float*)d_in[5];
    const float* vol = (const float*)d_in[9];
    float* out = (float*)d_out;

    // Stage constant weights (D2D memcpy nodes; capturable).
    cudaMemcpyToSymbolAsync(cW1, d_in[1], 3  * 32 * 4, 0, cudaMemcpyDeviceToDevice, 0);
    cudaMemcpyToSymbolAsync(cB1, d_in[2], 32 * 4,      0, cudaMemcpyDeviceToDevice, 0);
    cudaMemcpyToSymbolAsync(cW2, d_in[3], 32 * 32 * 4, 0, cudaMemcpyDeviceToDevice, 0);
    cudaMemcpyToSymbolAsync(cB2, d_in[4], 32 * 4,      0, cudaMemcpyDeviceToDevice, 0);
    cudaMemcpyToSymbolAsync(cB3, d_in[6], 32 * 4,      0, cudaMemcpyDeviceToDevice, 0);

    // Prepack final-layer pairs on device, then stage into constant memory.
    prep_kernel<<<1, 32>>>((const float*)d_in[7], (const float*)d_in[8]);
    void* sp = 0;
    cudaGetSymbolAddress(&sp, g_wf_scratch);
    cudaMemcpyToSymbolAsync(cWfP, sp, 66 * 8, 0, cudaMemcpyDeviceToDevice, 0);

    int npts = out_size;           // 2,097,152 points
    int npairs = npts / 2;         // 2 points per thread
    int grid = (npairs + BLK - 1) / BLK;

    deform_sample_kernel<<<grid, BLK>>>(x, W3g, vol, out, npairs);
}

// round 15
// speedup vs baseline: 1.1534x; 1.1534x over previous
#include <cuda_runtime.h>

// ---------------------------------------------------------------------------
// RModel_29257317221019: fused cos-MLP deform (3->32->32->32->3) + trilinear
// sample from 256^3 volume.
// R9 winner (2 pts/thread, f32x2 over output pairs, ALL weights __constant__,
// plain element indexing, __launch_bounds__(128,4)) with ONE change:
// constant arrays are natively typed ulonglong2 so every weight fetch is an
// immediate-offset 16B LDC.128 -> LDC instruction count halved, no IMADs.
// ---------------------------------------------------------------------------

typedef unsigned long long u64;

__device__ __forceinline__ void upk2(u64 v, float& lo, float& hi) {
    asm("mov.b64 {%0, %1}, %2;" : "=f"(lo), "=f"(hi) : "l"(v));
}
__device__ __forceinline__ u64 pk2(float lo, float hi) {
    u64 r; asm("mov.b64 %0, {%1, %2};" : "=l"(r) : "f"(lo), "f"(hi)); return r;
}
__device__ __forceinline__ u64 dup2(float v) {
    u64 r; asm("mov.b64 %0, {%1, %1};" : "=l"(r) : "f"(v)); return r;
}
__device__ __forceinline__ u64 ffma2(u64 a, u64 b, u64 c) {
    u64 r; asm("fma.rn.f32x2 %0, %1, %2, %3;" : "=l"(r) : "l"(a), "l"(b), "l"(c)); return r;
}

// Constant weights, natively ulonglong2: element access with compile-time
// indices -> immediate-offset LDC.128. Byte layouts = raw row-major floats.
//   cW1[c][q] = (pair 2q, pair 2q+1) of W1 row c      (q = d/4)
//   cW2[k][m] = (pair 2m, pair 2m+1) of W2 row k
__constant__ ulonglong2 cW1[3][8];
__constant__ ulonglong2 cB1[8];
__constant__ ulonglong2 cW2[32][8];
__constant__ ulonglong2 cB2[8];
__constant__ ulonglong2 cW3[32][8];
__constant__ ulonglong2 cB3[8];
// Final layer, prepacked by prep_kernel:
//   cWfP[k]  = ((Wf[k][0],Wf[k][1]), (Wf[k][2],0)),  k = 0..31
//   cWfP[32] = ((bf0,bf1), (bf2,0))
__constant__ ulonglong2 cWfP[33];

__device__ u64 g_wf_scratch[66];

__global__ void prep_kernel(const float* __restrict__ Wf,
                            const float* __restrict__ bf) {
    int k = threadIdx.x;
    if (k < 32) {
        g_wf_scratch[2 * k]     = pk2(Wf[3 * k + 0], Wf[3 * k + 1]);
        g_wf_scratch[2 * k + 1] = pk2(Wf[3 * k + 2], 0.0f);
    }
    if (k == 0) {
        g_wf_scratch[64] = pk2(bf[0], bf[1]);
        g_wf_scratch[65] = pk2(bf[2], 0.0f);
    }
}

#define BLK 128

__global__ __launch_bounds__(BLK, 4)
void deform_sample_kernel(
    const float* __restrict__ x,
    const float* __restrict__ vol,
    float* __restrict__ out,
    int npairs)
{
    int t = blockIdx.x * blockDim.x + threadIdx.x;
    if (t >= npairs) return;

    // Two consecutive points (x layout: 4 floats/point, coords in [0:3])
    const float4* x4 = reinterpret_cast<const float4*>(x);
    float4 XA = x4[2 * t + 0];
    float4 XB = x4[2 * t + 1];

    float hA[32], hB[32];
    u64 aA[16], aB[16];

    // ---- Layer 1: h = cos(c @ W1 + b1) ----
    {
        u64 cA0 = dup2(XA.x), cA1 = dup2(XA.y), cA2 = dup2(XA.z);
        u64 cB0 = dup2(XB.x), cB1v = dup2(XB.y), cB2v = dup2(XB.z);
#pragma unroll
        for (int q = 0; q < 8; q++) {           // d = 4q .. 4q+3
            ulonglong2 bb = cB1[q];
            u64 pA0 = bb.x, pA1 = bb.y, pB0 = bb.x, pB1 = bb.y;
            ulonglong2 w0 = cW1[0][q];
            ulonglong2 w1 = cW1[1][q];
            ulonglong2 w2 = cW1[2][q];
            pA0 = ffma2(cA0, w0.x, pA0);  pA1 = ffma2(cA0, w0.y, pA1);
            pB0 = ffma2(cB0, w0.x, pB0);  pB1 = ffma2(cB0, w0.y, pB1);
            pA0 = ffma2(cA1, w1.x, pA0);  pA1 = ffma2(cA1, w1.y, pA1);
            pB0 = ffma2(cB1v, w1.x, pB0); pB1 = ffma2(cB1v, w1.y, pB1);
            pA0 = ffma2(cA2, w2.x, pA0);  pA1 = ffma2(cA2, w2.y, pA1);
            pB0 = ffma2(cB2v, w2.x, pB0); pB1 = ffma2(cB2v, w2.y, pB1);
            float lo, hi;
            upk2(pA0, lo, hi); hA[4*q]   = __cosf(lo); hA[4*q+1] = __cosf(hi);
            upk2(pA1, lo, hi); hA[4*q+2] = __cosf(lo); hA[4*q+3] = __cosf(hi);
            upk2(pB0, lo, hi); hB[4*q]   = __cosf(lo); hB[4*q+1] = __cosf(hi);
            upk2(pB1, lo, hi); hB[4*q+2] = __cosf(lo); hB[4*q+3] = __cosf(hi);
        }
    }

    // ---- Layer 2: h = cos(h @ W2 + b2) ----
#pragma unroll
    for (int m = 0; m < 8; m++) {
        ulonglong2 b = cB2[m];
        aA[2*m] = b.x; aA[2*m+1] = b.y;
        aB[2*m] = b.x; aB[2*m+1] = b.y;
    }
#pragma unroll
    for (int k = 0; k < 32; k++) {
        u64 dA = dup2(hA[k]);
        u64 dB = dup2(hB[k]);
#pragma unroll
        for (int m = 0; m < 8; m++) {
            ulonglong2 w = cW2[k][m];
            aA[2*m]   = ffma2(dA, w.x, aA[2*m]);
            aA[2*m+1] = ffma2(dA, w.y, aA[2*m+1]);
            aB[2*m]   = ffma2(dB, w.x, aB[2*m]);
            aB[2*m+1] = ffma2(dB, w.y, aB[2*m+1]);
        }
    }
#pragma unroll
    for (int p = 0; p < 16; p++) {
        float lo, hi;
        upk2(aA[p], lo, hi); hA[2*p] = __cosf(lo); hA[2*p+1] = __cosf(hi);
        upk2(aB[p], lo, hi); hB[2*p] = __cosf(lo); hB[2*p+1] = __cosf(hi);
    }

    // ---- Layer 3: h = cos(h @ W3 + b3) ----
#pragma unroll
    for (int m = 0; m < 8; m++) {
        ulonglong2 b = cB3[m];
        aA[2*m] = b.x; aA[2*m+1] = b.y;
        aB[2*m] = b.x; aB[2*m+1] = b.y;
    }
#pragma unroll
    for (int k = 0; k < 32; k++) {
        u64 dA = dup2(hA[k]);
        u64 dB = dup2(hB[k]);
#pragma unroll
        for (int m = 0; m < 8; m++) {
            ulonglong2 w = cW3[k][m];
            aA[2*m]   = ffma2(dA, w.x, aA[2*m]);
            aA[2*m+1] = ffma2(dA, w.y, aA[2*m+1]);
            aB[2*m]   = ffma2(dB, w.x, aB[2*m]);
            aB[2*m+1] = ffma2(dB, w.y, aB[2*m+1]);
        }
    }
#pragma unroll
    for (int p = 0; p < 16; p++) {
        float lo, hi;
        upk2(aA[p], lo, hi); hA[2*p] = __cosf(lo); hA[2*p+1] = __cosf(hi);
        upk2(aB[p], lo, hi); hB[2*p] = __cosf(lo); hB[2*p+1] = __cosf(hi);
    }

    // ---- Final: coord = c + 5 * (h @ Wf + bf) ----
    float pxy[2][3];
    {
        ulonglong2 bb = cWfP[32];
        u64 eA01 = bb.x, eA2 = bb.y;
        u64 eB01 = bb.x, eB2 = bb.y;
#pragma unroll
        for (int k = 0; k < 32; k++) {
            ulonglong2 w = cWfP[k];         // (w01, w2x)
            u64 dA = dup2(hA[k]);
            u64 dB = dup2(hB[k]);
            eA01 = ffma2(dA, w.x, eA01);
            eA2  = ffma2(dA, w.y, eA2);
            eB01 = ffma2(dB, w.x, eB01);
            eB2  = ffma2(dB, w.y, eB2);
        }
        float f0, f1, f2, jk;
        upk2(eA01, f0, f1); upk2(eA2, f2, jk);
        pxy[0][0] = fmaf(5.0f, f0, XA.x);
        pxy[0][1] = fmaf(5.0f, f1, XA.y);
        pxy[0][2] = fmaf(5.0f, f2, XA.z);
        upk2(eB01, f0, f1); upk2(eB2, f2, jk);
        pxy[1][0] = fmaf(5.0f, f0, XB.x);
        pxy[1][1] = fmaf(5.0f, f1, XB.y);
        pxy[1][2] = fmaf(5.0f, f2, XB.z);
    }

    // ---- Trilinear sample (scalar per point) ----
    float res[2];
#pragma unroll
    for (int s = 0; s < 2; s++) {
        float cx = fminf(fmaxf(pxy[s][0], 0.0f), 255.0f);
        float cy = fminf(fmaxf(pxy[s][1], 0.0f), 255.0f);
        float cz = fminf(fmaxf(pxy[s][2], 0.0f), 255.0f);

        float fx0 = floorf(cx), fy0 = floorf(cy), fz0 = floorf(cz);
        int ix0 = (int)fx0, iy0 = (int)fy0, iz0 = (int)fz0;
        int ix1 = min(ix0 + 1, 255);
        int iy1 = min(iy0 + 1, 255);
        int iz1 = min(iz0 + 1, 255);

        float fx = cx - fx0, fy = cy - fy0, fz = cz - fz0;
        float gx = 1.0f - fx, gy = 1.0f - fy, gz = 1.0f - fz;

        int X0 = ix0 << 16, X1 = ix1 << 16;
        int Y0 = iy0 << 8,  Y1 = iy1 << 8;

        float v000 = __ldg(vol + (X0 + Y0 + iz0));
        float v100 = __ldg(vol + (X1 + Y0 + iz0));
        float v010 = __ldg(vol + (X0 + Y1 + iz0));
        float v001 = __ldg(vol + (X0 + Y0 + iz1));
        float v110 = __ldg(vol + (X1 + Y1 + iz0));
        float v101 = __ldg(vol + (X1 + Y0 + iz1));
        float v011 = __ldg(vol + (X0 + Y1 + iz1));
        float v111 = __ldg(vol + (X1 + Y1 + iz1));

        float r;
        r  = v000 * (gx * gy * gz);
        r += v100 * (fx * gy * gz);
        r += v010 * (gx * fy * gz);
        r += v001 * (gx * gy * fz);
        r += v110 * (fx * fy * gz);
        r += v101 * (fx * gy * fz);
        r += v011 * (gx * fy * fz);
        r += v111 * (fx * fy * fz);
        res[s] = r;
    }

    float2 o; o.x = res[0]; o.y = res[1];
    reinterpret_cast<float2*>(out)[t] = o;
}

extern "C" void kernel_launch(void* const* d_in, const int* in_sizes, int n_in,
                              void* d_out, int out_size) {
    const float* x   = (const float*)d_in[0];
    const float* vol = (const float*)d_in[9];
    float* out = (float*)d_out;

    // Stage weights into constant memory (D2D memcpy nodes; capturable).
    cudaMemcpyToSymbolAsync(cW1, d_in[1], 3  * 32 * 4, 0, cudaMemcpyDeviceToDevice, 0);
    cudaMemcpyToSymbolAsync(cB1, d_in[2], 32 * 4,      0, cudaMemcpyDeviceToDevice, 0);
    cudaMemcpyToSymbolAsync(cW2, d_in[3], 32 * 32 * 4, 0, cudaMemcpyDeviceToDevice, 0);
    cudaMemcpyToSymbolAsync(cB2, d_in[4], 32 * 4,      0, cudaMemcpyDeviceToDevice, 0);
    cudaMemcpyToSymbolAsync(cW3, d_in[5], 32 * 32 * 4, 0, cudaMemcpyDeviceToDevice, 0);
    cudaMemcpyToSymbolAsync(cB3, d_in[6], 32 * 4,      0, cudaMemcpyDeviceToDevice, 0);

    // Prepack final-layer pairs on device, then stage into constant memory.
    prep_kernel<<<1, 32>>>((const float*)d_in[7], (const float*)d_in[8]);
    void* sp = 0;
    cudaGetSymbolAddress(&sp, g_wf_scratch);
    cudaMemcpyToSymbolAsync(cWfP, sp, 66 * 8, 0, cudaMemcpyDeviceToDevice, 0);

    int npts = out_size;           // 2,097,152 points
    int npairs = npts / 2;         // 2 points per thread
    int grid = (npairs + BLK - 1) / BLK;

    deform_sample_kernel<<<grid, BLK>>>(x, vol, out, npairs);
}